// round 9
// baseline (speedup 1.0000x reference)
#include <cuda_runtime.h>
#include <cuda_fp16.h>
#include <cstdint>
#include <cstddef>

// ---------------- static device buffers (no runtime allocation) ----------------
// Unduplicated fp16 activation planes, chunk-major pre-swizzled: [k/32][4096 rows][64B]
__device__ __align__(256) __half g_X[4096 * 512];    // layer-0 input (16 chunks)
__device__ __align__(256) __half g_H1[4096 * 1024];  // hidden 1 (32 chunks)
__device__ __align__(256) __half g_H2[4096 * 1024];  // hidden 2 (32 chunks)
// W plane (single fp16), chunk-major pre-swizzled per layer:
// L0 @ 0 (4M el), L1 @ 4M (8M el), L2 @ 12M (4M el)
__device__ __align__(256) __half g_Wh[16 * 1024 * 1024];

// ---------------- helpers ----------------
__device__ __forceinline__ uint32_t smem_u32(const void* p) {
    uint32_t a;
    asm("{ .reg .u64 t; cvta.to.shared.u64 t, %1; cvt.u32.u64 %0, t; }" : "=r"(a) : "l"(p));
    return a;
}

#define MBAR_INIT(a, c) asm volatile("mbarrier.init.shared.b64 [%0], %1;" ::"r"(a), "r"(c) : "memory")
#define MBAR_EXPECT(a, n) \
    asm volatile("mbarrier.arrive.expect_tx.shared.b64 _, [%0], %1;" ::"r"(a), "r"(n) : "memory")
#define MBAR_ARRIVE(a) \
    asm volatile("mbarrier.arrive.release.cta.shared::cta.b64 _, [%0];" ::"r"(a) : "memory")
#define FENCE_ASYNC() asm volatile("fence.proxy.async.shared::cta;" ::: "memory")
#define CP_BULK(dst, src, bytes, mbar)                                                        \
    asm volatile(                                                                             \
        "cp.async.bulk.shared::cluster.global.mbarrier::complete_tx::bytes [%0], [%1], %2, [%3];" \
        ::"r"(dst), "l"(src), "r"(bytes), "r"(mbar) : "memory")
#define MBAR_WAIT(a, ph)                                                                           \
    do {                                                                                           \
        uint32_t _m = (a), _p = (ph), _d;                                                          \
        asm volatile(                                                                              \
            "{\n\t.reg .pred p;\n\t"                                                               \
            "mbarrier.try_wait.parity.acquire.cta.shared::cta.b64 p, [%1], %2;\n\t"                \
            "selp.b32 %0,1,0,p;\n\t}"                                                              \
            : "=r"(_d) : "r"(_m), "r"(_p) : "memory");                                             \
        if (!_d) {                                                                                 \
            asm volatile(                                                                          \
                "{\n\t.reg .pred P1;\n\t"                                                          \
                "WL%=:\n\t"                                                                        \
                "mbarrier.try_wait.parity.acquire.cta.shared::cta.b64 P1, [%0], %1, 0x989680;\n\t" \
                "@P1 bra.uni WD%=;\n\t"                                                            \
                "bra.uni WL%=;\n\t"                                                                \
                "WD%=:\n\t}" ::"r"(_m), "r"(_p) : "memory");                                       \
        }                                                                                          \
    } while (0)

__device__ __forceinline__ void ldsm4(uint32_t& r0, uint32_t& r1, uint32_t& r2, uint32_t& r3,
                                      uint32_t addr) {
    asm volatile("ldmatrix.sync.aligned.m8n8.x4.shared.b16 {%0,%1,%2,%3}, [%4];"
                 : "=r"(r0), "=r"(r1), "=r"(r2), "=r"(r3) : "r"(addr));
}

__device__ __forceinline__ void mma16816(float* c, const uint32_t* a, const uint32_t* b) {
    asm volatile(
        "mma.sync.aligned.m16n8k16.row.col.f32.f16.f16.f32 "
        "{%0,%1,%2,%3}, {%4,%5,%6,%7}, {%8,%9}, {%0,%1,%2,%3};"
        : "+f"(c[0]), "+f"(c[1]), "+f"(c[2]), "+f"(c[3])
        : "r"(a[0]), "r"(a[1]), "r"(a[2]), "r"(a[3]), "r"(b[0]), "r"(b[1]));
}

__device__ __forceinline__ uint32_t pkh2(float a, float b) {
    __half2 t = __floats2half2_rn(a, b);
    return *(uint32_t*)&t;
}

__device__ __forceinline__ uint32_t h2scale(uint32_t a, uint32_t s) {
    uint32_t r;
    asm("mul.rn.f16x2 %0, %1, %2;" : "=r"(r) : "r"(a), "r"(s));
    return r;
}

// in-tile swizzle: row*64 + ((seg ^ ((row>>1)&3))<<4)  (seg = 16B segment 0..3)
#define SWZ(row, seg) ((uint32_t)((row) * 64 + ((((seg) ^ (((row) >> 1) & 3))) << 4)))

// ---------------- weight convert (single fp16) into chunk-major pre-swizzled layout ---------
template <int N, int K_IN>
__global__ void wconv(const float* __restrict__ W, __half* __restrict__ hi) {
    constexpr int SEGS = K_IN / 8;
    int t = blockIdx.x * blockDim.x + threadIdx.x;
    if (t >= 8 * N * SEGS) return;
    int s8 = t % SEGS;
    int n = (t / SEGS) % N;
    int e = t / (N * SEGS);
    int i = s8 * 8;
    const float* src = W + ((size_t)e * N + n) * K_IN + i;
    float4 v0 = *(const float4*)src;
    float4 v1 = *(const float4*)(src + 4);
    uint4 H;
    H.x = pkh2(v0.x, v0.y);
    H.y = pkh2(v0.z, v0.w);
    H.z = pkh2(v1.x, v1.y);
    H.w = pkh2(v1.z, v1.w);
    int kg = e * K_IN + i;
    int chunk = kg >> 5, seg = (kg >> 3) & 3;
    size_t off = (size_t)chunk * (N * 64) + SWZ(n, seg);  // bytes
    *(uint4*)((char*)hi + off) = H;
}

// ---------------- x convert (fp32 -> fp16, pre-swizzled chunk-major, NO blend) --------------
__global__ void xconv(const float* __restrict__ x, __half* __restrict__ Ah) {
    constexpr int SEGS = 64;  // 512/8
    int idx = blockIdx.x * blockDim.x + threadIdx.x;
    if (idx >= 4096 * SEGS) return;
    int b = idx >> 6, s8 = idx & 63;
    int i = s8 * 8;
    const float* src = x + (size_t)b * 512 + i;
    float4 v0 = *(const float4*)src;
    float4 v1 = *(const float4*)(src + 4);
    uint4 H;
    H.x = pkh2(v0.x, v0.y);
    H.y = pkh2(v0.z, v0.w);
    H.z = pkh2(v1.x, v1.y);
    H.w = pkh2(v1.z, v1.w);
    int chunk = i >> 5, seg = (i >> 3) & 3;
    size_t off = (size_t)chunk * (4096 * 64) + SWZ(b, seg);  // bytes
    *(uint4*)((char*)Ah + off) = H;
}

// ---------------- GEMM: C(4096,N) = [blend ⊙ h](4096, 8*K_IN) x W^T ------------------------
// A plane is UNDUPLICATED h; blend applied to A fragments in-register (mul.rn.f16x2).
// CTA tile MT x NT x 32; 8 warps. 4-stage cp.async.bulk ring with full/empty mbarriers.
// OUTMODE: 0 = fp32 row-major out, 1 = fp16 pre-swizzled chunk-major A-plane (next layer).
template <int MT, int NT, int K_IN, int N, int OUTMODE, bool DO_ELU>
__global__ __launch_bounds__(256, 2) void gemm_mma(
    const __half* __restrict__ Ah, const __half* __restrict__ Wh,
    const float* __restrict__ blend, const float* __restrict__ Bias,
    void* __restrict__ outp) {
    constexpr int CPE = K_IN / 32;     // chunks per expert
    constexpr int NC = 8 * CPE;        // total chunks
    constexpr int NST = 4;
    constexpr int AB = MT * 64;        // bytes: A tile
    constexpr int BB = NT * 64;        // bytes: B tile
    constexpr int STG = AB + BB;
    constexpr int MB_OFF = NST * STG;  // full[s] at +8s, empty[s] at +8*NST+8s
    constexpr int BLS_OFF = MB_OFF + 128;  // fp16 blend table [MT][8]
    constexpr int MW = MT / 32;
    constexpr int WNC = NT * MW / 8;
    constexpr int NP = WNC / 16;
    constexpr int NTT = WNC / 8;
    constexpr size_t CHA = 4096 * 64;
    constexpr size_t CHB = (size_t)N * 64;

    extern __shared__ __align__(1024) char smem[];
    const uint32_t sb = smem_u32(smem);
    const int tid = threadIdx.x, wid = tid >> 5, lid = tid & 31;
    const int wm = wid % MW, wn = wid / MW;
    const int mBase = blockIdx.y * MT, nBase = blockIdx.x * NT;

    const uint32_t fullb = sb + MB_OFF;
    const uint32_t emptyb = sb + MB_OFF + 8 * NST;
    const uint32_t bls = sb + BLS_OFF;

    if (tid == 0) {
#pragma unroll
        for (int s = 0; s < NST; s++) {
            MBAR_INIT(fullb + 8 * s, 1);
            MBAR_INIT(emptyb + 8 * s, 8);
        }
        FENCE_ASYNC();
    }
    // stage fp16 blend table for this CTA's rows: [r][e]
    for (int i = tid; i < MT * 8; i += 256) {
        int r = i >> 3, e = i & 7;
        __half v = __float2half_rn(blend[(size_t)(mBase + r) * 8 + e]);
        *(__half*)(smem + BLS_OFF + i * 2) = v;
    }
    __syncthreads();

    auto issue = [&](int s, int c) {
        const uint32_t st = sb + s * STG;
        const uint32_t mb = fullb + 8 * s;
        MBAR_EXPECT(mb, STG);
        CP_BULK(st, (const char*)Ah + (size_t)(c & (CPE - 1)) * CHA + (size_t)mBase * 64, AB, mb);
        CP_BULK(st + AB, (const char*)Wh + (size_t)c * CHB + (size_t)nBase * 64, BB, mb);
    };

    if (tid == 0) {
#pragma unroll
        for (int s = 0; s < NST; s++) issue(s, s);
    }

    float acc[2][NTT][4];
#pragma unroll
    for (int a = 0; a < 2; a++)
#pragma unroll
        for (int b = 0; b < NTT; b++)
#pragma unroll
            for (int c = 0; c < 4; c++) acc[a][b][c] = 0.f;

    uint32_t sc[2][2];  // duplicated half2 blend scale per (mt, rowhalf), current expert

    for (int c = 0; c < NC; c++) {
        if ((c & (CPE - 1)) == 0) {
            const int e = c / CPE;
#pragma unroll
            for (int mt = 0; mt < 2; mt++)
#pragma unroll
                for (int h = 0; h < 2; h++) {
                    int r = wm * 32 + mt * 16 + (lid >> 2) + h * 8;
                    uint32_t v;
                    asm("ld.shared.u16 %0, [%1];"
                        : "=r"(v) : "r"(bls + (uint32_t)((r * 8 + e) * 2)));
                    sc[mt][h] = v * 0x00010001u;  // (s, s)
                }
        }
        const int s = c % NST;
        const int r = c / NST;
        MBAR_WAIT(fullb + 8 * s, r & 1);

        const uint32_t aB = sb + s * STG;
        const uint32_t bB = aB + AB;
        const int mat = lid >> 3, ri = lid & 7;
#pragma unroll
        for (int kk = 0; kk < 2; kk++) {
            uint32_t bh[NP][4];
#pragma unroll
            for (int p = 0; p < NP; p++) {
                int n = wn * WNC + p * 16 + ((mat >> 1) << 3) + ri;
                int seg = kk * 2 + (mat & 1);
                ldsm4(bh[p][0], bh[p][1], bh[p][2], bh[p][3], bB + SWZ(n, seg));
            }
#pragma unroll
            for (int mt = 0; mt < 2; mt++) {
                uint32_t ah[4];
                int r2 = wm * 32 + mt * 16 + ((mat & 1) << 3) + ri;
                int seg = kk * 2 + (mat >> 1);
                ldsm4(ah[0], ah[1], ah[2], ah[3], aB + SWZ(r2, seg));
                // blend-scale A fragment: regs 0,2 = row (lid>>2); regs 1,3 = row+8
                ah[0] = h2scale(ah[0], sc[mt][0]);
                ah[2] = h2scale(ah[2], sc[mt][0]);
                ah[1] = h2scale(ah[1], sc[mt][1]);
                ah[3] = h2scale(ah[3], sc[mt][1]);
#pragma unroll
                for (int nt = 0; nt < NTT; nt++) {
                    mma16816(acc[mt][nt], ah, &bh[nt >> 1][(nt & 1) * 2]);
                }
            }
        }
        if (lid == 0) MBAR_ARRIVE(emptyb + 8 * s);
        if (tid == 0) {
            int cc = c + NST;
            if (cc < NC) {
                MBAR_WAIT(emptyb + 8 * s, r & 1);
                issue(s, cc);
            }
        }
    }
    __syncthreads();  // all warps out of mainloop; stage smem now dead

    // ---- epilogue: blended bias + optional ELU ----
    float* biasS = (float*)smem;  // reuse stage region
    for (int i = tid; i < 8 * NT; i += 256)
        biasS[i] = Bias[(i / NT) * N + nBase + (i % NT)];
    __syncthreads();

#pragma unroll
    for (int mt = 0; mt < 2; mt++) {
#pragma unroll
        for (int hh = 0; hh < 2; hh++) {
            const int row = mBase + wm * 32 + mt * 16 + (lid >> 2) + hh * 8;
            float4 b0 = *(const float4*)(blend + (size_t)row * 8);
            float4 b1 = *(const float4*)(blend + (size_t)row * 8 + 4);
            float blv[8] = {b0.x, b0.y, b0.z, b0.w, b1.x, b1.y, b1.z, b1.w};
#pragma unroll
            for (int nt = 0; nt < NTT; nt++) {
                int cl = wn * WNC + nt * 8 + (lid & 3) * 2;  // tile-local col
                int col = nBase + cl;                        // global col
                float v0 = acc[mt][nt][hh * 2 + 0];
                float v1 = acc[mt][nt][hh * 2 + 1];
                float bb0 = 0.f, bb1 = 0.f;
#pragma unroll
                for (int e = 0; e < 8; e++) {
                    bb0 += blv[e] * biasS[e * NT + cl];
                    bb1 += blv[e] * biasS[e * NT + cl + 1];
                }
                v0 += bb0;
                v1 += bb1;
                if (DO_ELU) {
                    v0 = (v0 > 0.f) ? v0 : expm1f(v0);
                    v1 = (v1 > 0.f) ? v1 : expm1f(v1);
                }
                if (OUTMODE == 1) {
                    // write fp16 h directly in pre-swizzled chunk-major A-plane layout
                    size_t off = (size_t)(col >> 5) * CHA +
                                 (uint32_t)(SWZ(row, (col >> 3) & 3) + (col & 7) * 2);
                    *(uint32_t*)((char*)outp + off) = pkh2(v0, v1);
                } else {
                    *(float2*)((float*)outp + (size_t)row * N + col) = make_float2(v0, v1);
                }
            }
        }
    }
}

// ---------------- host ----------------
extern "C" void kernel_launch(void* const* d_in, const int* in_sizes, int n_in,
                              void* d_out, int out_size) {
    const float* blend = (const float*)d_in[0];  // (4096, 8)
    const float* x     = (const float*)d_in[1];  // (4096, 512)
    const float* W0    = (const float*)d_in[2];  // (8, 1024, 512)
    const float* B0    = (const float*)d_in[3];
    const float* W1    = (const float*)d_in[4];  // (8, 1024, 1024)
    const float* B1    = (const float*)d_in[5];
    const float* W2    = (const float*)d_in[6];  // (8, 512, 1024)
    const float* B2    = (const float*)d_in[7];
    float* out = (float*)d_out;                  // (4096, 512)

    __half *ax, *h1, *h2, *wh;
    cudaGetSymbolAddress((void**)&ax, g_X);
    cudaGetSymbolAddress((void**)&h1, g_H1);
    cudaGetSymbolAddress((void**)&h2, g_H2);
    cudaGetSymbolAddress((void**)&wh, g_Wh);

    // weight converts into chunk-major pre-swizzled layout
    wconv<1024, 512><<<(8 * 1024 * 64 + 255) / 256, 256>>>(W0, wh);
    wconv<1024, 1024><<<(8 * 1024 * 128 + 255) / 256, 256>>>(W1, wh + 4194304);
    wconv<512, 1024><<<(8 * 512 * 128 + 255) / 256, 256>>>(W2, wh + 12582912);

    constexpr int S_L01 = 4 * (128 * 64 + 128 * 64) + 128 + 2048;  // ~66.2KB
    constexpr int S_L2  = 4 * (64 * 64 + 128 * 64) + 128 + 2048;   // ~50.2KB
    cudaFuncSetAttribute(gemm_mma<128, 128, 512, 1024, 1, true>,
                         cudaFuncAttributeMaxDynamicSharedMemorySize, S_L01);
    cudaFuncSetAttribute(gemm_mma<128, 128, 1024, 1024, 1, true>,
                         cudaFuncAttributeMaxDynamicSharedMemorySize, S_L01);
    cudaFuncSetAttribute(gemm_mma<64, 128, 1024, 512, 0, false>,
                         cudaFuncAttributeMaxDynamicSharedMemorySize, S_L2);

    // layer 0: x plane -> h1 plane (pre-swizzled fp16), ELU
    xconv<<<(4096 * 64 + 255) / 256, 256>>>(x, ax);
    gemm_mma<128, 128, 512, 1024, 1, true><<<dim3(8, 32), 256, S_L01>>>(
        ax, wh, blend, B0, h1);
    // layer 1: h1 plane -> h2 plane, ELU
    gemm_mma<128, 128, 1024, 1024, 1, true><<<dim3(8, 32), 256, S_L01>>>(
        h1, wh + 4194304, blend, B1, h2);
    // layer 2: h2 plane -> fp32 out, linear
    gemm_mma<64, 128, 1024, 512, 0, false><<<dim3(4, 64), 256, S_L2>>>(
        h2, wh + 12582912, blend, B2, out);
}

// round 10
// speedup vs baseline: 1.0099x; 1.0099x over previous
#include <cuda_runtime.h>
#include <cuda_fp16.h>
#include <cstdint>
#include <cstddef>

// ---------------- static device buffers (no runtime allocation) ----------------
// Duplicated blend-folded A plane (fp16), chunk-major pre-swizzled: [k/32][4096 rows][64B]
__device__ __align__(256) __half g_Ah[4096 * 8192];
// W plane (single fp16), chunk-major pre-swizzled per layer:
// L0 @ 0 (4M el), L1 @ 4M (8M el), L2 @ 12M (4M el)
__device__ __align__(256) __half g_Wh[16 * 1024 * 1024];
__device__ __align__(256) __half g_h16[4096 * 1024];  // fp16 hidden activations

// ---------------- helpers ----------------
__device__ __forceinline__ uint32_t smem_u32(const void* p) {
    uint32_t a;
    asm("{ .reg .u64 t; cvta.to.shared.u64 t, %1; cvt.u32.u64 %0, t; }" : "=r"(a) : "l"(p));
    return a;
}

#define MBAR_INIT(a, c) asm volatile("mbarrier.init.shared.b64 [%0], %1;" ::"r"(a), "r"(c) : "memory")
#define MBAR_EXPECT(a, n) \
    asm volatile("mbarrier.arrive.expect_tx.shared.b64 _, [%0], %1;" ::"r"(a), "r"(n) : "memory")
#define MBAR_ARRIVE(a) \
    asm volatile("mbarrier.arrive.release.cta.shared::cta.b64 _, [%0];" ::"r"(a) : "memory")
#define FENCE_ASYNC() asm volatile("fence.proxy.async.shared::cta;" ::: "memory")
#define CP_BULK(dst, src, bytes, mbar)                                                        \
    asm volatile(                                                                             \
        "cp.async.bulk.shared::cluster.global.mbarrier::complete_tx::bytes [%0], [%1], %2, [%3];" \
        ::"r"(dst), "l"(src), "r"(bytes), "r"(mbar) : "memory")
#define MBAR_WAIT(a, ph)                                                                           \
    do {                                                                                           \
        uint32_t _m = (a), _p = (ph), _d;                                                          \
        asm volatile(                                                                              \
            "{\n\t.reg .pred p;\n\t"                                                               \
            "mbarrier.try_wait.parity.acquire.cta.shared::cta.b64 p, [%1], %2;\n\t"                \
            "selp.b32 %0,1,0,p;\n\t}"                                                              \
            : "=r"(_d) : "r"(_m), "r"(_p) : "memory");                                             \
        if (!_d) {                                                                                 \
            asm volatile(                                                                          \
                "{\n\t.reg .pred P1;\n\t"                                                          \
                "WL%=:\n\t"                                                                        \
                "mbarrier.try_wait.parity.acquire.cta.shared::cta.b64 P1, [%0], %1, 0x989680;\n\t" \
                "@P1 bra.uni WD%=;\n\t"                                                            \
                "bra.uni WL%=;\n\t"                                                                \
                "WD%=:\n\t}" ::"r"(_m), "r"(_p) : "memory");                                       \
        }                                                                                          \
    } while (0)

__device__ __forceinline__ void ldsm4(uint32_t& r0, uint32_t& r1, uint32_t& r2, uint32_t& r3,
                                      uint32_t addr) {
    asm volatile("ldmatrix.sync.aligned.m8n8.x4.shared.b16 {%0,%1,%2,%3}, [%4];"
                 : "=r"(r0), "=r"(r1), "=r"(r2), "=r"(r3) : "r"(addr));
}

__device__ __forceinline__ void mma16816(float* c, const uint32_t* a, const uint32_t* b) {
    asm volatile(
        "mma.sync.aligned.m16n8k16.row.col.f32.f16.f16.f32 "
        "{%0,%1,%2,%3}, {%4,%5,%6,%7}, {%8,%9}, {%0,%1,%2,%3};"
        : "+f"(c[0]), "+f"(c[1]), "+f"(c[2]), "+f"(c[3])
        : "r"(a[0]), "r"(a[1]), "r"(a[2]), "r"(a[3]), "r"(b[0]), "r"(b[1]));
}

__device__ __forceinline__ uint32_t pkh2(float a, float b) {
    __half2 t = __floats2half2_rn(a, b);
    return *(uint32_t*)&t;
}

// in-tile swizzle: row*64 + ((seg ^ ((row>>1)&3))<<4)  (seg = 16B segment 0..3)
#define SWZ(row, seg) ((uint32_t)((row) * 64 + ((((seg) ^ (((row) >> 1) & 3))) << 4)))

// ---------------- weight convert (single fp16) into chunk-major pre-swizzled layout ---------
template <int N, int K_IN>
__global__ void wconv(const float* __restrict__ W, __half* __restrict__ hi) {
    constexpr int SEGS = K_IN / 8;
    int t = blockIdx.x * blockDim.x + threadIdx.x;
    if (t >= 8 * N * SEGS) return;
    int s8 = t % SEGS;
    int n = (t / SEGS) % N;
    int e = t / (N * SEGS);
    int i = s8 * 8;
    const float* src = W + ((size_t)e * N + n) * K_IN + i;
    float4 v0 = *(const float4*)src;
    float4 v1 = *(const float4*)(src + 4);
    uint4 H;
    H.x = pkh2(v0.x, v0.y);
    H.y = pkh2(v0.z, v0.w);
    H.z = pkh2(v1.x, v1.y);
    H.w = pkh2(v1.z, v1.w);
    int kg = e * K_IN + i;
    int chunk = kg >> 5, seg = (kg >> 3) & 3;
    size_t off = (size_t)chunk * (N * 64) + SWZ(n, seg);  // bytes
    *(uint4*)((char*)hi + off) = H;
}

// ---------------- activation fold from fp32 x: A[b, e*512+i] = blend[b,e]*x[b,i] ------------
__global__ void prep512(const float* __restrict__ x, const float* __restrict__ blend,
                        __half* __restrict__ Ah) {
    constexpr int SEGS = 64;  // 512/8
    int idx = blockIdx.x * blockDim.x + threadIdx.x;
    if (idx >= 4096 * SEGS) return;
    int b = idx / SEGS, s8 = idx % SEGS;
    int i = s8 * 8;
    const float* src = x + (size_t)b * 512 + i;
    float4 v0 = *(const float4*)src;
    float4 v1 = *(const float4*)(src + 4);
    float4 w0 = *(const float4*)(blend + (size_t)b * 8);
    float4 w1 = *(const float4*)(blend + (size_t)b * 8 + 4);
    float wv[8] = {w0.x, w0.y, w0.z, w0.w, w1.x, w1.y, w1.z, w1.w};
#pragma unroll
    for (int e = 0; e < 8; e++) {
        float s = wv[e];
        uint4 H;
        H.x = pkh2(v0.x * s, v0.y * s);
        H.y = pkh2(v0.z * s, v0.w * s);
        H.z = pkh2(v1.x * s, v1.y * s);
        H.w = pkh2(v1.z * s, v1.w * s);
        int kg = e * 512 + i;
        int chunk = kg >> 5, seg = (kg >> 3) & 3;
        size_t off = (size_t)chunk * (4096 * 64) + SWZ(b, seg);  // bytes
        *(uint4*)((char*)Ah + off) = H;
    }
}

// ---------------- activation fold from fp16 h: A[b, e*1024+i] = blend[b,e]*h[b,i] -----------
__global__ void prep_h(const __half* __restrict__ h, const float* __restrict__ blend,
                       __half* __restrict__ Ah) {
    constexpr int K_IN = 1024;
    constexpr int SEGS = 128;  // 1024/8
    int idx = blockIdx.x * blockDim.x + threadIdx.x;
    if (idx >= 4096 * SEGS) return;
    int b = idx / SEGS, s8 = idx % SEGS;
    int i = s8 * 8;
    uint4 raw = *(const uint4*)(h + (size_t)b * K_IN + i);
    float2 f0 = __half22float2(*(__half2*)&raw.x);
    float2 f1 = __half22float2(*(__half2*)&raw.y);
    float2 f2 = __half22float2(*(__half2*)&raw.z);
    float2 f3 = __half22float2(*(__half2*)&raw.w);
    float4 w0 = *(const float4*)(blend + (size_t)b * 8);
    float4 w1 = *(const float4*)(blend + (size_t)b * 8 + 4);
    float wv[8] = {w0.x, w0.y, w0.z, w0.w, w1.x, w1.y, w1.z, w1.w};
#pragma unroll
    for (int e = 0; e < 8; e++) {
        float s = wv[e];
        uint4 H;
        H.x = pkh2(f0.x * s, f0.y * s);
        H.y = pkh2(f1.x * s, f1.y * s);
        H.z = pkh2(f2.x * s, f2.y * s);
        H.w = pkh2(f3.x * s, f3.y * s);
        int kg = e * K_IN + i;
        int chunk = kg >> 5, seg = (kg >> 3) & 3;
        size_t off = (size_t)chunk * (4096 * 64) + SWZ(b, seg);  // bytes
        *(uint4*)((char*)Ah + off) = H;
    }
}

// ---------------- GEMM: C(4096,N) = A(4096,K) x W^T, single-product fp16 -------------------
// CTA tile MT x NT x 32; 8 warps arranged MWARPS x (8/MWARPS); warp tile (MT/MWARPS) x WNC.
// NST-stage cp.async.bulk ring with full/empty mbarriers.
template <int MT, int NT, int MWARPS, int NST, int MAXB, int K, int N, bool OUT_HALF, bool DO_ELU>
__global__ __launch_bounds__(256, MAXB) void gemm_mma(
    const __half* __restrict__ Ah, const __half* __restrict__ Wh,
    const float* __restrict__ blend, const float* __restrict__ Bias,
    void* __restrict__ outp) {
    constexpr int NC = K / 32;
    constexpr int AB = MT * 64;   // bytes: A tile
    constexpr int BB = NT * 64;   // bytes: B tile
    constexpr int STG = AB + BB;
    constexpr int MB_OFF = NST * STG;  // full[s] at +8s, empty[s] at +8*NST+8s
    constexpr int NW = 8 / MWARPS;     // warps along N
    constexpr int WM = MT / MWARPS;    // warp rows
    constexpr int MTL = WM / 16;       // m16 tiles per warp
    constexpr int WNC = NT / NW;       // warp cols
    constexpr int NP = WNC / 16;       // ldmatrix.x4 B loads per kk
    constexpr int NTT = WNC / 8;       // n8 tiles per warp
    constexpr size_t CHA = 4096 * 64;
    constexpr size_t CHB = (size_t)N * 64;

    extern __shared__ __align__(1024) char smem[];
    const uint32_t sb = smem_u32(smem);
    const int tid = threadIdx.x, wid = tid >> 5, lid = tid & 31;
    const int wm = wid % MWARPS, wn = wid / MWARPS;
    const int mBase = blockIdx.y * MT, nBase = blockIdx.x * NT;

    const uint32_t fullb = sb + MB_OFF;
    const uint32_t emptyb = sb + MB_OFF + 8 * NST;

    if (tid == 0) {
#pragma unroll
        for (int s = 0; s < NST; s++) {
            MBAR_INIT(fullb + 8 * s, 1);
            MBAR_INIT(emptyb + 8 * s, 8);
        }
        FENCE_ASYNC();
    }
    __syncthreads();

    auto issue = [&](int s, int c) {
        const uint32_t st = sb + s * STG;
        const uint32_t mb = fullb + 8 * s;
        MBAR_EXPECT(mb, STG);
        CP_BULK(st,      (const char*)Ah + (size_t)c * CHA + (size_t)mBase * 64, AB, mb);
        CP_BULK(st + AB, (const char*)Wh + (size_t)c * CHB + (size_t)nBase * 64, BB, mb);
    };

    if (tid == 0) {
#pragma unroll
        for (int s = 0; s < NST; s++) issue(s, s);
    }

    float acc[MTL][NTT][4];
#pragma unroll
    for (int a = 0; a < MTL; a++)
#pragma unroll
        for (int b = 0; b < NTT; b++)
#pragma unroll
            for (int c = 0; c < 4; c++) acc[a][b][c] = 0.f;

    for (int c = 0; c < NC; c++) {
        const int s = c % NST;
        const int r = c / NST;
        MBAR_WAIT(fullb + 8 * s, r & 1);

        const uint32_t aB = sb + s * STG;
        const uint32_t bB = aB + AB;
        const int mat = lid >> 3, ri = lid & 7;
#pragma unroll
        for (int kk = 0; kk < 2; kk++) {
            uint32_t bh[NP][4];
#pragma unroll
            for (int p = 0; p < NP; p++) {
                int n = wn * WNC + p * 16 + ((mat >> 1) << 3) + ri;
                int seg = kk * 2 + (mat & 1);
                ldsm4(bh[p][0], bh[p][1], bh[p][2], bh[p][3], bB + SWZ(n, seg));
            }
#pragma unroll
            for (int mt = 0; mt < MTL; mt++) {
                uint32_t ah[4];
                int r2 = wm * WM + mt * 16 + ((mat & 1) << 3) + ri;
                int seg = kk * 2 + (mat >> 1);
                ldsm4(ah[0], ah[1], ah[2], ah[3], aB + SWZ(r2, seg));
#pragma unroll
                for (int nt = 0; nt < NTT; nt++) {
                    mma16816(acc[mt][nt], ah, &bh[nt >> 1][(nt & 1) * 2]);
                }
            }
        }
        if (lid == 0) MBAR_ARRIVE(emptyb + 8 * s);
        if (tid == 0) {
            int cc = c + NST;
            if (cc < NC) {
                MBAR_WAIT(emptyb + 8 * s, r & 1);
                issue(s, cc);
            }
        }
    }
    __syncthreads();  // all warps out of mainloop; stage smem now dead

    // ---- epilogue: blended bias + optional ELU ----
    float* biasS = (float*)smem;
    for (int i = tid; i < 8 * NT; i += 256)
        biasS[i] = Bias[(i / NT) * N + nBase + (i % NT)];
    __syncthreads();

#pragma unroll
    for (int mt = 0; mt < MTL; mt++) {
#pragma unroll
        for (int hh = 0; hh < 2; hh++) {
            const int row = mBase + wm * WM + mt * 16 + (lid >> 2) + hh * 8;
            float4 b0 = *(const float4*)(blend + (size_t)row * 8);
            float4 b1 = *(const float4*)(blend + (size_t)row * 8 + 4);
            float blv[8] = {b0.x, b0.y, b0.z, b0.w, b1.x, b1.y, b1.z, b1.w};
#pragma unroll
            for (int nt = 0; nt < NTT; nt++) {
                int col = wn * WNC + nt * 8 + (lid & 3) * 2;
                float v0 = acc[mt][nt][hh * 2 + 0];
                float v1 = acc[mt][nt][hh * 2 + 1];
                float bb0 = 0.f, bb1 = 0.f;
#pragma unroll
                for (int e = 0; e < 8; e++) {
                    bb0 += blv[e] * biasS[e * NT + col];
                    bb1 += blv[e] * biasS[e * NT + col + 1];
                }
                v0 += bb0;
                v1 += bb1;
                if (DO_ELU) {
                    v0 = (v0 > 0.f) ? v0 : expm1f(v0);
                    v1 = (v1 > 0.f) ? v1 : expm1f(v1);
                }
                if (OUT_HALF) {
                    *(uint32_t*)((__half*)outp + (size_t)row * N + nBase + col) = pkh2(v0, v1);
                } else {
                    *(float2*)((float*)outp + (size_t)row * N + nBase + col) =
                        make_float2(v0, v1);
                }
            }
        }
    }
}

// ---------------- host ----------------
extern "C" void kernel_launch(void* const* d_in, const int* in_sizes, int n_in,
                              void* d_out, int out_size) {
    const float* blend = (const float*)d_in[0];  // (4096, 8)
    const float* x     = (const float*)d_in[1];  // (4096, 512)
    const float* W0    = (const float*)d_in[2];  // (8, 1024, 512)
    const float* B0    = (const float*)d_in[3];
    const float* W1    = (const float*)d_in[4];  // (8, 1024, 1024)
    const float* B1    = (const float*)d_in[5];
    const float* W2    = (const float*)d_in[6];  // (8, 512, 1024)
    const float* B2    = (const float*)d_in[7];
    float* out = (float*)d_out;                  // (4096, 512)

    __half *ah, *wh, *h16;
    cudaGetSymbolAddress((void**)&ah, g_Ah);
    cudaGetSymbolAddress((void**)&wh, g_Wh);
    cudaGetSymbolAddress((void**)&h16, g_h16);

    // weight converts into chunk-major pre-swizzled layout
    wconv<1024, 512><<<(8 * 1024 * 64 + 255) / 256, 256>>>(W0, wh);
    wconv<1024, 1024><<<(8 * 1024 * 128 + 255) / 256, 256>>>(W1, wh + 4194304);
    wconv<512, 1024><<<(8 * 512 * 128 + 255) / 256, 256>>>(W2, wh + 12582912);

    // layers 0/1: CTA 128x256, warp 64x64, occ 1, 6 stages (~144.1KB)
    constexpr int S_BIG = 6 * (128 * 64 + 256 * 64) + 128;
    // layer 2: CTA 64x128, warp 32x32, occ 2, 6 stages (~72.1KB)
    constexpr int S_L2 = 6 * (64 * 64 + 128 * 64) + 128;
    cudaFuncSetAttribute(gemm_mma<128, 256, 2, 6, 1, 4096, 1024, true, true>,
                         cudaFuncAttributeMaxDynamicSharedMemorySize, S_BIG);
    cudaFuncSetAttribute(gemm_mma<128, 256, 2, 6, 1, 8192, 1024, true, true>,
                         cudaFuncAttributeMaxDynamicSharedMemorySize, S_BIG);
    cudaFuncSetAttribute(gemm_mma<64, 128, 2, 6, 2, 8192, 512, false, false>,
                         cudaFuncAttributeMaxDynamicSharedMemorySize, S_L2);

    // layer 0: (4096,512) -> fp16 h (4096,1024), ELU
    prep512<<<(4096 * 64 + 255) / 256, 256>>>(x, blend, ah);
    gemm_mma<128, 256, 2, 6, 1, 4096, 1024, true, true><<<dim3(4, 32), 256, S_BIG>>>(
        ah, wh, blend, B0, h16);
    // layer 1: fp16 h -> fp16 h, ELU
    prep_h<<<(4096 * 128 + 255) / 256, 256>>>(h16, blend, ah);
    gemm_mma<128, 256, 2, 6, 1, 8192, 1024, true, true><<<dim3(4, 32), 256, S_BIG>>>(
        ah, wh + 4194304, blend, B1, h16);
    // layer 2: fp16 h -> fp32 out, linear
    prep_h<<<(4096 * 128 + 255) / 256, 256>>>(h16, blend, ah);
    gemm_mma<64, 128, 2, 6, 2, 8192, 512, false, false><<<dim3(4, 64), 256, S_L2>>>(
        ah, wh + 12582912, blend, B2, out);
}

// round 11
// speedup vs baseline: 1.0451x; 1.0348x over previous
#include <cuda_runtime.h>
#include <cuda_fp16.h>
#include <cstdint>
#include <cstddef>

// ---------------- static device buffers (no runtime allocation) ----------------
// Unduplicated fp16 activation planes, chunk-major pre-swizzled: [k/32][4096 rows][64B]
__device__ __align__(256) __half g_X[4096 * 512];    // layer-0 input (16 chunks)
__device__ __align__(256) __half g_H1[4096 * 1024];  // hidden 1 (32 chunks)
__device__ __align__(256) __half g_H2[4096 * 1024];  // hidden 2 (32 chunks)
// W plane (single fp16), chunk-major pre-swizzled per layer:
// L0 @ 0 (4M el), L1 @ 4M (8M el), L2 @ 12M (4M el)
__device__ __align__(256) __half g_Wh[16 * 1024 * 1024];

// ---------------- helpers ----------------
__device__ __forceinline__ uint32_t smem_u32(const void* p) {
    uint32_t a;
    asm("{ .reg .u64 t; cvta.to.shared.u64 t, %1; cvt.u32.u64 %0, t; }" : "=r"(a) : "l"(p));
    return a;
}

#define MBAR_INIT(a, c) asm volatile("mbarrier.init.shared.b64 [%0], %1;" ::"r"(a), "r"(c) : "memory")
#define MBAR_EXPECT(a, n) \
    asm volatile("mbarrier.arrive.expect_tx.shared.b64 _, [%0], %1;" ::"r"(a), "r"(n) : "memory")
#define MBAR_ARRIVE(a) \
    asm volatile("mbarrier.arrive.release.cta.shared::cta.b64 _, [%0];" ::"r"(a) : "memory")
#define FENCE_ASYNC() asm volatile("fence.proxy.async.shared::cta;" ::: "memory")
#define CP_BULK(dst, src, bytes, mbar)                                                        \
    asm volatile(                                                                             \
        "cp.async.bulk.shared::cluster.global.mbarrier::complete_tx::bytes [%0], [%1], %2, [%3];" \
        ::"r"(dst), "l"(src), "r"(bytes), "r"(mbar) : "memory")
#define MBAR_WAIT(a, ph)                                                                           \
    do {                                                                                           \
        uint32_t _m = (a), _p = (ph), _d;                                                          \
        asm volatile(                                                                              \
            "{\n\t.reg .pred p;\n\t"                                                               \
            "mbarrier.try_wait.parity.acquire.cta.shared::cta.b64 p, [%1], %2;\n\t"                \
            "selp.b32 %0,1,0,p;\n\t}"                                                              \
            : "=r"(_d) : "r"(_m), "r"(_p) : "memory");                                             \
        if (!_d) {                                                                                 \
            asm volatile(                                                                          \
                "{\n\t.reg .pred P1;\n\t"                                                          \
                "WL%=:\n\t"                                                                        \
                "mbarrier.try_wait.parity.acquire.cta.shared::cta.b64 P1, [%0], %1, 0x989680;\n\t" \
                "@P1 bra.uni WD%=;\n\t"                                                            \
                "bra.uni WL%=;\n\t"                                                                \
                "WD%=:\n\t}" ::"r"(_m), "r"(_p) : "memory");                                       \
        }                                                                                          \
    } while (0)

__device__ __forceinline__ void ldsm4(uint32_t& r0, uint32_t& r1, uint32_t& r2, uint32_t& r3,
                                      uint32_t addr) {
    asm volatile("ldmatrix.sync.aligned.m8n8.x4.shared.b16 {%0,%1,%2,%3}, [%4];"
                 : "=r"(r0), "=r"(r1), "=r"(r2), "=r"(r3) : "r"(addr));
}

__device__ __forceinline__ void mma16816(float* c, const uint32_t* a, const uint32_t* b) {
    asm volatile(
        "mma.sync.aligned.m16n8k16.row.col.f32.f16.f16.f32 "
        "{%0,%1,%2,%3}, {%4,%5,%6,%7}, {%8,%9}, {%0,%1,%2,%3};"
        : "+f"(c[0]), "+f"(c[1]), "+f"(c[2]), "+f"(c[3])
        : "r"(a[0]), "r"(a[1]), "r"(a[2]), "r"(a[3]), "r"(b[0]), "r"(b[1]));
}

__device__ __forceinline__ uint32_t pkh2(float a, float b) {
    __half2 t = __floats2half2_rn(a, b);
    return *(uint32_t*)&t;
}

// in-tile swizzle: row*64 + ((seg ^ ((row>>1)&3))<<4)  (seg = 16B segment 0..3)
#define SWZ(row, seg) ((uint32_t)((row) * 64 + ((((seg) ^ (((row) >> 1) & 3))) << 4)))

// ---------------- weight convert (single fp16) into chunk-major pre-swizzled layout ---------
template <int N, int K_IN>
__global__ void wconv(const float* __restrict__ W, __half* __restrict__ hi) {
    constexpr int SEGS = K_IN / 8;
    int t = blockIdx.x * blockDim.x + threadIdx.x;
    if (t >= 8 * N * SEGS) return;
    int s8 = t % SEGS;
    int n = (t / SEGS) % N;
    int e = t / (N * SEGS);
    int i = s8 * 8;
    const float* src = W + ((size_t)e * N + n) * K_IN + i;
    float4 v0 = *(const float4*)src;
    float4 v1 = *(const float4*)(src + 4);
    uint4 H;
    H.x = pkh2(v0.x, v0.y);
    H.y = pkh2(v0.z, v0.w);
    H.z = pkh2(v1.x, v1.y);
    H.w = pkh2(v1.z, v1.w);
    int kg = e * K_IN + i;
    int chunk = kg >> 5, seg = (kg >> 3) & 3;
    size_t off = (size_t)chunk * (N * 64) + SWZ(n, seg);  // bytes
    *(uint4*)((char*)hi + off) = H;
}

// ---------------- x convert (fp32 -> fp16, pre-swizzled chunk-major, NO blend) --------------
__global__ void xconv(const float* __restrict__ x, __half* __restrict__ Ah) {
    constexpr int SEGS = 64;  // 512/8
    int idx = blockIdx.x * blockDim.x + threadIdx.x;
    if (idx >= 4096 * SEGS) return;
    int b = idx >> 6, s8 = idx & 63;
    int i = s8 * 8;
    const float* src = x + (size_t)b * 512 + i;
    float4 v0 = *(const float4*)src;
    float4 v1 = *(const float4*)(src + 4);
    uint4 H;
    H.x = pkh2(v0.x, v0.y);
    H.y = pkh2(v0.z, v0.w);
    H.z = pkh2(v1.x, v1.y);
    H.w = pkh2(v1.z, v1.w);
    int chunk = i >> 5, seg = (i >> 3) & 3;
    size_t off = (size_t)chunk * (4096 * 64) + SWZ(b, seg);  // bytes
    *(uint4*)((char*)Ah + off) = H;
}

// ---------------- GEMM: C(4096,N) = [blend ⊙ h](4096, 8*K_IN) x W^T ------------------------
// A plane is UNDUPLICATED plain-fp16 h. Blend applied via telescoping accumulator rescale:
// before expert e (e>=1): acc *= bl[e-1]/bl[e]; after loop: acc *= bl[7]. Exact fp32 blend.
// CTA tile MT x NT x 32; 8 warps (MT/32 x ...); 4-stage cp.async.bulk ring.
// OUTMODE: 0 = fp32 row-major out, 1 = fp16 pre-swizzled chunk-major plane (next layer).
template <int MT, int NT, int K_IN, int N, int OUTMODE, bool DO_ELU>
__global__ __launch_bounds__(256, 2) void gemm_mma(
    const __half* __restrict__ Ah, const __half* __restrict__ Wh,
    const float* __restrict__ blend, const float* __restrict__ Bias,
    void* __restrict__ outp) {
    constexpr int CPE = K_IN / 32;     // chunks per expert
    constexpr int NC = 8 * CPE;        // total chunks
    constexpr int NST = 4;
    constexpr int AB = MT * 64;        // bytes: A tile
    constexpr int BB = NT * 64;        // bytes: B tile
    constexpr int STG = AB + BB;
    constexpr int MB_OFF = NST * STG;  // full[s] at +8s, empty[s] at +8*NST+8s
    constexpr int RT_OFF = MB_OFF + 128;  // fp32 ratio table [MT][8]
    constexpr int MW = MT / 32;        // warps along M
    constexpr int WNC = NT * MW / 8;   // warp N extent
    constexpr int NP = WNC / 16;
    constexpr int NTT = WNC / 8;
    constexpr size_t CHA = 4096 * 64;
    constexpr size_t CHB = (size_t)N * 64;

    extern __shared__ __align__(1024) char smem[];
    const uint32_t sb = smem_u32(smem);
    const int tid = threadIdx.x, wid = tid >> 5, lid = tid & 31;
    const int wm = wid % MW, wn = wid / MW;
    const int mBase = blockIdx.y * MT, nBase = blockIdx.x * NT;

    const uint32_t fullb = sb + MB_OFF;
    const uint32_t emptyb = sb + MB_OFF + 8 * NST;
    float* rtS = (float*)(smem + RT_OFF);

    if (tid == 0) {
#pragma unroll
        for (int s = 0; s < NST; s++) {
            MBAR_INIT(fullb + 8 * s, 1);
            MBAR_INIT(emptyb + 8 * s, 8);
        }
        FENCE_ASYNC();
    }
    // ratio table: rtS[r*8+e] = bl'[e-1]/bl'[e] (e>=1); rtS[r*8+0] = bl'[7] (final scale)
    for (int i = tid; i < MT * 8; i += 256) {
        int r = i >> 3, e = i & 7;
        const float* bl = blend + (size_t)(mBase + r) * 8;
        float v;
        if (e == 0) {
            v = fmaxf(bl[7], 1e-30f);
        } else {
            v = fmaxf(bl[e - 1], 1e-30f) / fmaxf(bl[e], 1e-30f);
        }
        rtS[i] = v;
    }
    __syncthreads();

    auto issue = [&](int s, int c) {
        const uint32_t st = sb + s * STG;
        const uint32_t mb = fullb + 8 * s;
        MBAR_EXPECT(mb, STG);
        CP_BULK(st, (const char*)Ah + (size_t)(c & (CPE - 1)) * CHA + (size_t)mBase * 64, AB, mb);
        CP_BULK(st + AB, (const char*)Wh + (size_t)c * CHB + (size_t)nBase * 64, BB, mb);
    };

    if (tid == 0) {
#pragma unroll
        for (int s = 0; s < NST; s++) issue(s, s);
    }

    float acc[2][NTT][4];
#pragma unroll
    for (int a = 0; a < 2; a++)
#pragma unroll
        for (int b = 0; b < NTT; b++)
#pragma unroll
            for (int c = 0; c < 4; c++) acc[a][b][c] = 0.f;

    const int rl0 = (lid >> 2);  // base row-in-tile component

    for (int c = 0; c < NC; c++) {
        // expert boundary: rescale accumulators by bl[e-1]/bl[e] (per row, fp32)
        if (c > 0 && (c & (CPE - 1)) == 0) {
            const int e = c / CPE;
#pragma unroll
            for (int mt = 0; mt < 2; mt++)
#pragma unroll
                for (int h = 0; h < 2; h++) {
                    int rloc = wm * 32 + mt * 16 + rl0 + h * 8;
                    float f = rtS[rloc * 8 + e];
#pragma unroll
                    for (int nt = 0; nt < NTT; nt++) {
                        acc[mt][nt][h * 2 + 0] *= f;
                        acc[mt][nt][h * 2 + 1] *= f;
                    }
                }
        }
        const int s = c % NST;
        const int r = c / NST;
        MBAR_WAIT(fullb + 8 * s, r & 1);

        const uint32_t aB = sb + s * STG;
        const uint32_t bB = aB + AB;
        const int mat = lid >> 3, ri = lid & 7;
#pragma unroll
        for (int kk = 0; kk < 2; kk++) {
            uint32_t bh[NP][4];
#pragma unroll
            for (int p = 0; p < NP; p++) {
                int n = wn * WNC + p * 16 + ((mat >> 1) << 3) + ri;
                int seg = kk * 2 + (mat & 1);
                ldsm4(bh[p][0], bh[p][1], bh[p][2], bh[p][3], bB + SWZ(n, seg));
            }
#pragma unroll
            for (int mt = 0; mt < 2; mt++) {
                uint32_t ah[4];
                int r2 = wm * 32 + mt * 16 + ((mat & 1) << 3) + ri;
                int seg = kk * 2 + (mat >> 1);
                ldsm4(ah[0], ah[1], ah[2], ah[3], aB + SWZ(r2, seg));
#pragma unroll
                for (int nt = 0; nt < NTT; nt++) {
                    mma16816(acc[mt][nt], ah, &bh[nt >> 1][(nt & 1) * 2]);
                }
            }
        }
        if (lid == 0) MBAR_ARRIVE(emptyb + 8 * s);
        if (tid == 0) {
            int cc = c + NST;
            if (cc < NC) {
                MBAR_WAIT(emptyb + 8 * s, r & 1);
                issue(s, cc);
            }
        }
    }

    // final telescoping scale: acc *= bl'[7]
#pragma unroll
    for (int mt = 0; mt < 2; mt++)
#pragma unroll
        for (int h = 0; h < 2; h++) {
            int rloc = wm * 32 + mt * 16 + rl0 + h * 8;
            float f = rtS[rloc * 8 + 0];
#pragma unroll
            for (int nt = 0; nt < NTT; nt++) {
                acc[mt][nt][h * 2 + 0] *= f;
                acc[mt][nt][h * 2 + 1] *= f;
            }
        }

    __syncthreads();  // all warps out of mainloop; stage smem now dead

    // ---- epilogue: blended bias + optional ELU ----
    float* biasS = (float*)smem;  // reuse stage region (rtS region untouched but no longer needed)
    for (int i = tid; i < 8 * NT; i += 256)
        biasS[i] = Bias[(i / NT) * N + nBase + (i % NT)];
    __syncthreads();

#pragma unroll
    for (int mt = 0; mt < 2; mt++) {
#pragma unroll
        for (int hh = 0; hh < 2; hh++) {
            const int row = mBase + wm * 32 + mt * 16 + rl0 + hh * 8;
            float4 b0 = *(const float4*)(blend + (size_t)row * 8);
            float4 b1 = *(const float4*)(blend + (size_t)row * 8 + 4);
            float blv[8] = {b0.x, b0.y, b0.z, b0.w, b1.x, b1.y, b1.z, b1.w};
#pragma unroll
            for (int nt = 0; nt < NTT; nt++) {
                int cl = wn * WNC + nt * 8 + (lid & 3) * 2;  // tile-local col
                int col = nBase + cl;                        // global col
                float v0 = acc[mt][nt][hh * 2 + 0];
                float v1 = acc[mt][nt][hh * 2 + 1];
                float bb0 = 0.f, bb1 = 0.f;
#pragma unroll
                for (int e = 0; e < 8; e++) {
                    bb0 += blv[e] * biasS[e * NT + cl];
                    bb1 += blv[e] * biasS[e * NT + cl + 1];
                }
                v0 += bb0;
                v1 += bb1;
                if (DO_ELU) {
                    v0 = (v0 > 0.f) ? v0 : expm1f(v0);
                    v1 = (v1 > 0.f) ? v1 : expm1f(v1);
                }
                if (OUTMODE == 1) {
                    // write fp16 h directly in pre-swizzled chunk-major plane layout
                    size_t off = (size_t)(col >> 5) * CHA +
                                 (uint32_t)(SWZ(row, (col >> 3) & 3) + (col & 7) * 2);
                    *(uint32_t*)((char*)outp + off) = pkh2(v0, v1);
                } else {
                    *(float2*)((float*)outp + (size_t)row * N + col) = make_float2(v0, v1);
                }
            }
        }
    }
}

// ---------------- host ----------------
extern "C" void kernel_launch(void* const* d_in, const int* in_sizes, int n_in,
                              void* d_out, int out_size) {
    const float* blend = (const float*)d_in[0];  // (4096, 8)
    const float* x     = (const float*)d_in[1];  // (4096, 512)
    const float* W0    = (const float*)d_in[2];  // (8, 1024, 512)
    const float* B0    = (const float*)d_in[3];
    const float* W1    = (const float*)d_in[4];  // (8, 1024, 1024)
    const float* B1    = (const float*)d_in[5];
    const float* W2    = (const float*)d_in[6];  // (8, 512, 1024)
    const float* B2    = (const float*)d_in[7];
    float* out = (float*)d_out;                  // (4096, 512)

    __half *ax, *h1, *h2, *wh;
    cudaGetSymbolAddress((void**)&ax, g_X);
    cudaGetSymbolAddress((void**)&h1, g_H1);
    cudaGetSymbolAddress((void**)&h2, g_H2);
    cudaGetSymbolAddress((void**)&wh, g_Wh);

    // weight converts into chunk-major pre-swizzled layout
    wconv<1024, 512><<<(8 * 1024 * 64 + 255) / 256, 256>>>(W0, wh);
    wconv<1024, 1024><<<(8 * 1024 * 128 + 255) / 256, 256>>>(W1, wh + 4194304);
    wconv<512, 1024><<<(8 * 512 * 128 + 255) / 256, 256>>>(W2, wh + 12582912);

    // layers 0/1: CTA 128x128, 4 stages (64KB) + mbar + 4KB ratio table
    constexpr int S_L01 = 4 * (128 * 64 + 128 * 64) + 128 + 128 * 8 * 4;  // ~68.2KB
    // layer 2: CTA 64x128 (48KB stages) + mbar + 2KB ratio table
    constexpr int S_L2 = 4 * (64 * 64 + 128 * 64) + 128 + 64 * 8 * 4;     // ~50.2KB
    cudaFuncSetAttribute(gemm_mma<128, 128, 512, 1024, 1, true>,
                         cudaFuncAttributeMaxDynamicSharedMemorySize, S_L01);
    cudaFuncSetAttribute(gemm_mma<128, 128, 1024, 1024, 1, true>,
                         cudaFuncAttributeMaxDynamicSharedMemorySize, S_L01);
    cudaFuncSetAttribute(gemm_mma<64, 128, 1024, 512, 0, false>,
                         cudaFuncAttributeMaxDynamicSharedMemorySize, S_L2);

    // layer 0: x plane -> h1 plane (pre-swizzled fp16), ELU
    xconv<<<(4096 * 64 + 255) / 256, 256>>>(x, ax);
    gemm_mma<128, 128, 512, 1024, 1, true><<<dim3(8, 32), 256, S_L01>>>(
        ax, wh, blend, B0, h1);
    // layer 1: h1 plane -> h2 plane, ELU
    gemm_mma<128, 128, 1024, 1024, 1, true><<<dim3(8, 32), 256, S_L01>>>(
        h1, wh + 4194304, blend, B1, h2);
    // layer 2: h2 plane -> fp32 out, linear
    gemm_mma<64, 128, 1024, 512, 0, false><<<dim3(4, 64), 256, S_L2>>>(
        h2, wh + 12582912, blend, B2, out);
}